// round 13
// baseline (speedup 1.0000x reference)
#include <cuda_runtime.h>
#include <cstdint>

// Problem constants (fixed by the reference)
#define VOCAB 32000
#define D_EMB 768
#define SEQ   2048
#define BATCH 16
#define F4    (D_EMB / 4)        // 192 float4 per row

// Geometry: grid = (128, 6, 2), 256 threads (8 warps).
//   blockIdx.x -> chunk of 16 s-rows
//   blockIdx.y -> slice of 32 f4 columns (128 d values)
//   blockIdx.z -> batch half (8 batches per block, one per warp)
// Warp w owns ONE batch row-group and loops over the 16 s values:
// its consecutive stores are 3KB apart (same DRAM page), instead of the
// previous 6MB-strided b-innermost pattern that touched 16 far pages
// round-robin. 1536 blocks = the empirically best CTA count (R11).
#define S_PER_BLK 16
#define C_PER_BLK 32              // float4 columns per block
#define D_PER_BLK (C_PER_BLK * 4) // 128
#define B_PER_BLK 8
#define THREADS   256

// ---------------------------------------------------------------------------
// Semantics (from the reference's where() inversion):
//   out[b,s,d] = pe[s,d]
//              + (input_ids[b,s]==0     ? W_tok[d,0]+b_tok[d] : 0)
//              + (segment_label[b,s]==0 ? W_seg[d,0]+b_seg[d] : 0)
//
// R12 -> R13 change: loop order swapped for DRAM page locality. Each warp
// streams 16 stores through ONE contiguous 48KB output region (s-innermost)
// instead of 16 stores 6MB apart (b-innermost). pe loads are shared across
// the 8 warps of a block via L1 (identical addresses). Masks are one 16-bit
// ballot word per warp, register-resident.
// ---------------------------------------------------------------------------
__global__ void __launch_bounds__(THREADS)
bebert_fused_kernel(const int*   __restrict__ input_ids,
                    const int*   __restrict__ segment_label,
                    const float* __restrict__ W_tok,
                    const float* __restrict__ b_tok,
                    const float* __restrict__ W_seg,
                    const float* __restrict__ b_seg,
                    const float* __restrict__ pe,
                    float*       __restrict__ out)
{
    __shared__ __align__(16) float s_tok[D_PER_BLK];
    __shared__ __align__(16) float s_seg[D_PER_BLK];

    const int t      = threadIdx.x;
    const int w      = t >> 5;                  // warp 0..7
    const int l      = t & 31;                  // lane = f4 column in slice
    const int s0     = blockIdx.x * S_PER_BLK;
    const int cslice = blockIdx.y;              // 0..5
    const int b      = blockIdx.z * B_PER_BLK + w;   // this warp's batch
    const int d0     = cslice * D_PER_BLK;

    // --- prep: combined vectors for this slice (threads 0..127) ---
    if (t < D_PER_BLK) {
        const int d = d0 + t;
        s_tok[t] = __ldg(W_tok + (size_t)d * VOCAB) + __ldg(b_tok + d);
        s_seg[t] = __ldg(W_seg + (size_t)d * 3)     + __ldg(b_seg + d);
    }

    // --- masks in registers: 16 s-predicates for this warp's batch ---
    // Lanes 0..15 and 16..31 load the same 16 ids (valid addresses, bits
    // replicate); we use the low 16 bits of the ballot.
    unsigned tokm, segm;
    {
        const int sl  = l & 15;
        const int row = b * SEQ + s0 + sl;
        tokm = __ballot_sync(0xFFFFFFFFu, __ldg(input_ids     + row) == 0);
        segm = __ballot_sync(0xFFFFFFFFu, __ldg(segment_label + row) == 0);
    }
    __syncthreads();

    const int c = cslice * C_PER_BLK + l;       // global f4 column

    const float4 tv = reinterpret_cast<const float4*>(s_tok)[l];
    const float4 sv = reinterpret_cast<const float4*>(s_seg)[l];

    // pe base for (s0, c); advances by one row (F4 float4s) per s.
    const float4* pe4 = reinterpret_cast<const float4*>(pe) + (size_t)s0 * F4 + c;
    // out base for (b, s0, c); same per-s stride. 16 stores span 48KB.
    float4* o = reinterpret_cast<float4*>(out)
              + ((size_t)b * SEQ + s0) * F4 + c;

#pragma unroll 4
    for (int sr = 0; sr < S_PER_BLK; ++sr) {
        float4 r = pe4[(size_t)sr * F4];        // L1-hit for 7 of 8 warps
        if ((tokm >> sr) & 1u) { r.x += tv.x; r.y += tv.y; r.z += tv.z; r.w += tv.w; }
        if ((segm >> sr) & 1u) { r.x += sv.x; r.y += sv.y; r.z += sv.z; r.w += sv.w; }
        __stcs(o + (size_t)sr * F4, r);         // streaming, 512B/warp, page-local
    }
}

// ---------------------------------------------------------------------------
// Launch. Input order (metadata): input_ids, segment_label, W_tok, b_tok,
// W_seg, b_seg, pe. ids arrive as int32 (jax x64 disabled). Output fp32.
// ---------------------------------------------------------------------------
extern "C" void kernel_launch(void* const* d_in, const int* in_sizes, int n_in,
                              void* d_out, int out_size) {
    const int*   input_ids     = (const int*)  d_in[0];
    const int*   segment_label = (const int*)  d_in[1];
    const float* W_tok         = (const float*)d_in[2];
    const float* b_tok         = (const float*)d_in[3];
    const float* W_seg         = (const float*)d_in[4];
    const float* b_seg         = (const float*)d_in[5];
    const float* pe            = (const float*)d_in[6];
    float*       out           = (float*)d_out;

    dim3 grid(SEQ / S_PER_BLK, F4 / C_PER_BLK, BATCH / B_PER_BLK); // (128,6,2)
    bebert_fused_kernel<<<grid, THREADS>>>(
        input_ids, segment_label, W_tok, b_tok, W_seg, b_seg, pe, out);
}